// round 4
// baseline (speedup 1.0000x reference)
#include <cuda_runtime.h>
#include <cstdint>
#include <cstddef>

// Problem constants
#define RH 512
#define RB 64
#define RS 2048
#define RI 512

// ---------------------------------------------------------------------------
// f32x2 packed helpers (sm_100a)
// ---------------------------------------------------------------------------
__device__ __forceinline__ void ffma2(unsigned long long &d,
                                      unsigned long long a,
                                      unsigned long long b) {
    asm("fma.rn.f32x2 %0, %1, %2, %0;" : "+l"(d) : "l"(a), "l"(b));
}
__device__ __forceinline__ unsigned long long dup2(float x) {
    unsigned long long r;
    asm("mov.b64 %0, {%1, %1};" : "=l"(r) : "f"(x));
    return r;
}
__device__ __forceinline__ float2 unpack2(unsigned long long v) {
    float2 r;
    asm("mov.b64 {%0, %1}, %2;" : "=f"(r.x), "=f"(r.y) : "l"(v));
    return r;
}
__device__ __forceinline__ float lo_plus_hi(unsigned long long v) {
    float2 r = unpack2(v);
    return r.x + r.y;
}

// ---------------------------------------------------------------------------
// Phase 1: x_proj GEMM (unchanged)
// ---------------------------------------------------------------------------
#define BN 128
#define BK 16
#define AS_PITCH 68
#define WS_PITCH 136

__global__ void __launch_bounds__(256)
rnn_xproj(const float* __restrict__ A,
          const float* __restrict__ Wih,
          const float* __restrict__ bih,
          const float* __restrict__ bhh,
          float* __restrict__ out)
{
    __shared__ float As[BK * AS_PITCH];
    __shared__ float Ws[BK * WS_PITCH];

    const int tid = threadIdx.x;
    const int s  = blockIdx.y;
    const int h0 = blockIdx.x * BN;
    const int r0 = s * RB;

    const int tm0 = (tid >> 4) << 2;
    const int tn  = (tid & 15) << 2;

    const int a_r = tid >> 2;
    const int a_k = (tid & 3) << 2;

    const float* Arow  = A   + ((size_t)a_r * RS + s) * RI;
    const float* Wrow0 = Wih + (size_t)(h0 + a_r) * RI;
    const float* Wrow1 = Wih + (size_t)(h0 + 64 + a_r) * RI;

    unsigned long long c2[4][4];
    #pragma unroll
    for (int i = 0; i < 4; i++)
        #pragma unroll
        for (int j = 0; j < 4; j++) c2[i][j] = 0ull;

    for (int k0 = 0; k0 < RI; k0 += BK) {
        float4 av = *reinterpret_cast<const float4*>(Arow  + k0 + a_k);
        float4 w0 = *reinterpret_cast<const float4*>(Wrow0 + k0 + a_k);
        float4 w1 = *reinterpret_cast<const float4*>(Wrow1 + k0 + a_k);
        As[(a_k + 0) * AS_PITCH + a_r] = av.x;
        As[(a_k + 1) * AS_PITCH + a_r] = av.y;
        As[(a_k + 2) * AS_PITCH + a_r] = av.z;
        As[(a_k + 3) * AS_PITCH + a_r] = av.w;
        Ws[(a_k + 0) * WS_PITCH + a_r] = w0.x;
        Ws[(a_k + 1) * WS_PITCH + a_r] = w0.y;
        Ws[(a_k + 2) * WS_PITCH + a_r] = w0.z;
        Ws[(a_k + 3) * WS_PITCH + a_r] = w0.w;
        Ws[(a_k + 0) * WS_PITCH + 64 + a_r] = w1.x;
        Ws[(a_k + 1) * WS_PITCH + 64 + a_r] = w1.y;
        Ws[(a_k + 2) * WS_PITCH + 64 + a_r] = w1.z;
        Ws[(a_k + 3) * WS_PITCH + 64 + a_r] = w1.w;
        __syncthreads();
        #pragma unroll
        for (int kk = 0; kk < BK; kk++) {
            float4 a = *reinterpret_cast<const float4*>(&As[kk * AS_PITCH + tm0]);
            ulonglong2 bA = *reinterpret_cast<const ulonglong2*>(&Ws[kk * WS_PITCH + tn]);
            ulonglong2 bB = *reinterpret_cast<const ulonglong2*>(&Ws[kk * WS_PITCH + 64 + tn]);
            unsigned long long am0 = dup2(a.x), am1 = dup2(a.y),
                               am2 = dup2(a.z), am3 = dup2(a.w);
            ffma2(c2[0][0], am0, bA.x); ffma2(c2[0][1], am0, bA.y);
            ffma2(c2[0][2], am0, bB.x); ffma2(c2[0][3], am0, bB.y);
            ffma2(c2[1][0], am1, bA.x); ffma2(c2[1][1], am1, bA.y);
            ffma2(c2[1][2], am1, bB.x); ffma2(c2[1][3], am1, bB.y);
            ffma2(c2[2][0], am2, bA.x); ffma2(c2[2][1], am2, bA.y);
            ffma2(c2[2][2], am2, bB.x); ffma2(c2[2][3], am2, bB.y);
            ffma2(c2[3][0], am3, bA.x); ffma2(c2[3][1], am3, bA.y);
            ffma2(c2[3][2], am3, bB.x); ffma2(c2[3][3], am3, bB.y);
        }
        __syncthreads();
    }

    const int hA = h0 + tn;
    const int hB = h0 + 64 + tn;
    float4 biA, biB;
    {
        float4 b1 = *reinterpret_cast<const float4*>(bih + hA);
        float4 b2 = *reinterpret_cast<const float4*>(bhh + hA);
        biA = make_float4(b1.x + b2.x, b1.y + b2.y, b1.z + b2.z, b1.w + b2.w);
        float4 b3 = *reinterpret_cast<const float4*>(bih + hB);
        float4 b4 = *reinterpret_cast<const float4*>(bhh + hB);
        biB = make_float4(b3.x + b4.x, b3.y + b4.y, b3.z + b4.z, b3.w + b4.w);
    }
    #pragma unroll
    for (int im = 0; im < 4; im++) {
        int r = r0 + tm0 + im;
        float2 uA0 = unpack2(c2[im][0]);
        float2 uA1 = unpack2(c2[im][1]);
        float2 uB0 = unpack2(c2[im][2]);
        float2 uB1 = unpack2(c2[im][3]);
        float4 oA = make_float4(uA0.x + biA.x, uA0.y + biA.y, uA1.x + biA.z, uA1.y + biA.w);
        float4 oB = make_float4(uB0.x + biB.x, uB0.y + biB.y, uB1.x + biB.z, uB1.y + biB.w);
        *reinterpret_cast<float4*>(&out[(size_t)r * RH + hA]) = oA;
        *reinterpret_cast<float4*>(&out[(size_t)r * RH + hB]) = oB;
    }
}

// ---------------------------------------------------------------------------
// Phase 2: recurrence. 16 clusters x 8 CTAs, 512 threads/CTA.
// W_hh register-resident. TRIPLE-buffered h, NO cluster barrier:
// per step: mbar full-wait (acquire.cluster) -> FMA -> reduce/tanh -> stage ->
// sync -> broadcast f4/thread to remote Hv[(s+1)%3] -> sync -> elected:
// fence.acq_rel.cluster + 8 remote mbarrier.arrive.release.cluster.
// Data-dependency bounds CTA skew to <=1 step; 3 buffers make overwrite safe.
// ---------------------------------------------------------------------------
#define CSZ 8
#define HBUF_F4 544                 // 4 b * 8 kg blocks * 17 float4
#define STAGE_F4 68

__device__ __forceinline__ uint32_t smem_u32(const void* p) {
    return (uint32_t)__cvta_generic_to_shared(p);
}
__device__ __forceinline__ uint32_t mapa_u32(uint32_t addr, uint32_t rank) {
    uint32_t r;
    asm("mapa.shared::cluster.u32 %0, %1, %2;" : "=r"(r) : "r"(addr), "r"(rank));
    return r;
}
__device__ __forceinline__ void st_cluster_v4(uint32_t addr, float4 v) {
    asm volatile("st.shared::cluster.v4.f32 [%0], {%1,%2,%3,%4};"
                 :: "r"(addr), "f"(v.x), "f"(v.y), "f"(v.z), "f"(v.w) : "memory");
}
__device__ __forceinline__ void mbar_init(uint32_t addr, uint32_t count) {
    asm volatile("mbarrier.init.shared.b64 [%0], %1;" :: "r"(addr), "r"(count) : "memory");
}
__device__ __forceinline__ void mbar_arrive_remote(uint32_t addr) {
    asm volatile("mbarrier.arrive.release.cluster.shared::cluster.b64 _, [%0];"
                 :: "r"(addr) : "memory");
}
__device__ __forceinline__ void mbar_wait_parity_acq_cluster(uint32_t addr, uint32_t parity) {
    uint32_t done;
    asm volatile(
        "{\n\t"
        ".reg .pred p;\n\t"
        "mbarrier.try_wait.parity.acquire.cluster.shared::cta.b64 p, [%1], %2;\n\t"
        "selp.b32 %0, 1, 0, p;\n\t"
        "}"
        : "=r"(done) : "r"(addr), "r"(parity) : "memory");
    if (!done) {
        asm volatile(
            "{\n\t"
            ".reg .pred P1;\n\t"
            "WAIT_LOOP_%=:\n\t"
            "mbarrier.try_wait.parity.acquire.cluster.shared::cta.b64 P1, [%0], %1, 0x989680;\n\t"
            "@P1 bra.uni WAIT_DONE_%=;\n\t"
            "bra.uni WAIT_LOOP_%=;\n\t"
            "WAIT_DONE_%=:\n\t"
            "}"
            :: "r"(addr), "r"(parity) : "memory");
    }
}
__device__ __forceinline__ void fence_cluster() {
    asm volatile("fence.acq_rel.cluster;" ::: "memory");
}
__device__ __forceinline__ void cluster_sync_once() {
    asm volatile("barrier.cluster.arrive.aligned;" ::: "memory");
    asm volatile("barrier.cluster.wait.aligned;" ::: "memory");
}

__global__ void __cluster_dims__(CSZ, 1, 1) __launch_bounds__(512, 1)
rnn_recur(const float* __restrict__ w_hh,
          const float* __restrict__ state,
          float* __restrict__ out,
          int has_tail)
{
    __shared__ float4 Hv[3 * HBUF_F4];
    __shared__ float4 Stg[STAGE_F4];
    __shared__ unsigned long long fullbar;

    const int tid = threadIdx.x;
    const int w = tid >> 5;
    const int l = tid & 31;
    uint32_t rank;
    asm("mov.u32 %0, %%cluster_ctarank;" : "=r"(rank));
    const int cl = blockIdx.x >> 3;
    const int j0 = (int)rank * 64;
    const int b0 = cl * 4;

    const int jj = l & 3;
    const int kg = l >> 2;
    const int j_local = (w << 2) + jj;

    // --- W_hh slice into registers ---
    unsigned long long wreg[32];
    {
        const ulonglong2* ws = reinterpret_cast<const ulonglong2*>(
            w_hh + ((size_t)(j0 + j_local) << 9) + ((size_t)kg << 6));
        #pragma unroll
        for (int i = 0; i < 16; i++) {
            ulonglong2 v = ws[i];
            wreg[2 * i]     = v.x;
            wreg[2 * i + 1] = v.y;
        }
    }

    // --- initial state into buf0 ---
    for (int v = tid; v < 4 * 128; v += 512) {
        int b  = v >> 7;
        int kv = v & 127;
        float4 x = __ldg(reinterpret_cast<const float4*>(state) + ((size_t)(b0 + b) << 7) + kv);
        Hv[((b << 3) + (kv >> 4)) * 17 + (kv & 15)] = x;
    }
    if (tid == 0) mbar_init(smem_u32(&fullbar), CSZ);   // 8 arrives per phase
    __syncthreads();
    cluster_sync_once();   // mbar init + buf0 visible cluster-wide

    const bool act = (l < 16);
    const int ob = l >> 2;
    const size_t row_stride = (size_t)RB * RH;
    const size_t oidx = (size_t)(b0 + ob) * RH + (size_t)(j0 + j_local);
    const int kglob = j0 + j_local;

    float* stg_f = reinterpret_cast<float*>(Stg);
    const int stg_idx = ob * 68 + j_local;

    // broadcast mapping: one float4 per thread per step
    const int bc_c   = tid >> 6;
    const int bc_idx = tid & 63;
    const int bc_ob  = bc_idx >> 4;
    const int bc_i   = bc_idx & 15;
    const int src_f4 = bc_ob * 17 + bc_i;
    const uint32_t dst_off = (uint32_t)((((bc_ob << 3) + (int)rank) * 17 + bc_i) * 16);
    const uint32_t remBase = mapa_u32(smem_u32(Hv) + dst_off, (uint32_t)bc_c);
    const uint32_t mybar = smem_u32(&fullbar);
    const uint32_t bufBytes = HBUF_F4 * 16u;

    const int offb0 = (kg) * 17;
    const int offb1 = (8 + kg) * 17;
    const int offb2 = (16 + kg) * 17;
    const int offb3 = (24 + kg) * 17;

    float xp_cur = act ? __ldg(out + oidx) : 0.f;

    int cur = 0, nxt = 1;
    uint32_t parity = 0;

    for (int s = 0; s < RS; ++s) {
        const float4* base = Hv + cur * HBUF_F4;
        unsigned long long p0 = 0ull, p1 = 0ull, p2 = 0ull, p3 = 0ull;
        unsigned long long q0 = 0ull, q1 = 0ull, q2 = 0ull, q3 = 0ull;
        #pragma unroll
        for (int i = 0; i < 16; i++) {
            ulonglong2 h0 = *reinterpret_cast<const ulonglong2*>(base + offb0 + i);
            ulonglong2 h1 = *reinterpret_cast<const ulonglong2*>(base + offb1 + i);
            ulonglong2 h2 = *reinterpret_cast<const ulonglong2*>(base + offb2 + i);
            ulonglong2 h3 = *reinterpret_cast<const ulonglong2*>(base + offb3 + i);
            unsigned long long w0 = wreg[2 * i], w1 = wreg[2 * i + 1];
            ffma2(p0, w0, h0.x); ffma2(q0, w1, h0.y);
            ffma2(p1, w0, h1.x); ffma2(q1, w1, h1.y);
            ffma2(p2, w0, h2.x); ffma2(q2, w1, h2.y);
            ffma2(p3, w0, h3.x); ffma2(q3, w1, h3.y);
        }
        float a0 = lo_plus_hi(p0) + lo_plus_hi(q0);
        float a1 = lo_plus_hi(p1) + lo_plus_hi(q1);
        float a2 = lo_plus_hi(p2) + lo_plus_hi(q2);
        float a3 = lo_plus_hi(p3) + lo_plus_hi(q3);
        #pragma unroll
        for (int off = 4; off < 32; off <<= 1) {
            a0 += __shfl_xor_sync(0xffffffffu, a0, off);
            a1 += __shfl_xor_sync(0xffffffffu, a1, off);
            a2 += __shfl_xor_sync(0xffffffffu, a2, off);
            a3 += __shfl_xor_sync(0xffffffffu, a3, off);
        }

        float y = 0.f;
        if (act) {
            float acc = (ob == 0) ? a0 : ((ob == 1) ? a1 : ((ob == 2) ? a2 : a3));
            y = tanhf(xp_cur + acc);
            stg_f[stg_idx] = y;
        }

        if (s + 1 < RS) {
            __syncthreads();   // staging ready

            // broadcast one float4 to remote Hv[nxt]
            {
                float4 v = Stg[src_f4];
                st_cluster_v4(remBase + (uint32_t)nxt * bufBytes, v);
            }

            __syncthreads();   // all broadcast stores issued

            if (tid == 0) {
                fence_cluster();
                #pragma unroll
                for (int c = 0; c < CSZ; c++)
                    mbar_arrive_remote(mapa_u32(mybar, (uint32_t)c));
            }
        }

        // GMEM traffic in the wait shadow
        float xp_next = 0.f;
        if (act) {
            out[oidx + (size_t)s * row_stride] = y;
            if (has_tail && (s == RS - 1))
                out[(size_t)RS * RB * RH + (size_t)kglob * RB + (size_t)(b0 + ob)] = y;
            if (s + 1 < RS)
                xp_next = __ldg(out + oidx + (size_t)(s + 1) * row_stride);
        }

        if (s + 1 < RS) {
            mbar_wait_parity_acq_cluster(mybar, parity);
            parity ^= 1u;
        }

        cur = nxt;
        nxt = nxt + 1; if (nxt == 3) nxt = 0;
        xp_cur = xp_next;
    }
}

// ---------------------------------------------------------------------------
// Launch
// ---------------------------------------------------------------------------
extern "C" void kernel_launch(void* const* d_in, const int* in_sizes, int n_in,
                              void* d_out, int out_size)
{
    const float* inputs = (const float*)d_in[0];
    const float* state  = (const float*)d_in[1];
    const float* w_ih   = (const float*)d_in[2];
    const float* b_ih   = (const float*)d_in[3];
    const float* w_hh   = (const float*)d_in[4];
    const float* b_hh   = (const float*)d_in[5];
    float* out = (float*)d_out;

    dim3 g1(RH / BN, RS);   // (4, 2048)
    rnn_xproj<<<g1, 256>>>(inputs, w_ih, b_ih, b_hh, out);

    int has_tail = (out_size > RS * RB * RH) ? 1 : 0;
    rnn_recur<<<128, 512>>>(w_hh, state, out, has_tail);
}

// round 5
// speedup vs baseline: 1.1065x; 1.1065x over previous
#include <cuda_runtime.h>
#include <cstdint>
#include <cstddef>

// Problem constants
#define RH 512
#define RB 64
#define RS 2048
#define RI 512

// ---------------------------------------------------------------------------
// f32x2 packed helpers (sm_100a)
// ---------------------------------------------------------------------------
__device__ __forceinline__ void ffma2(unsigned long long &d,
                                      unsigned long long a,
                                      unsigned long long b) {
    asm("fma.rn.f32x2 %0, %1, %2, %0;" : "+l"(d) : "l"(a), "l"(b));
}
__device__ __forceinline__ unsigned long long dup2(float x) {
    unsigned long long r;
    asm("mov.b64 %0, {%1, %1};" : "=l"(r) : "f"(x));
    return r;
}
__device__ __forceinline__ float2 unpack2(unsigned long long v) {
    float2 r;
    asm("mov.b64 {%0, %1}, %2;" : "=f"(r.x), "=f"(r.y) : "l"(v));
    return r;
}
__device__ __forceinline__ float lo_plus_hi(unsigned long long v) {
    float2 r = unpack2(v);
    return r.x + r.y;
}

// ---------------------------------------------------------------------------
// Phase 1: x_proj GEMM (unchanged)
// ---------------------------------------------------------------------------
#define BN 128
#define BK 16
#define AS_PITCH 68
#define WS_PITCH 136

__global__ void __launch_bounds__(256)
rnn_xproj(const float* __restrict__ A,
          const float* __restrict__ Wih,
          const float* __restrict__ bih,
          const float* __restrict__ bhh,
          float* __restrict__ out)
{
    __shared__ float As[BK * AS_PITCH];
    __shared__ float Ws[BK * WS_PITCH];

    const int tid = threadIdx.x;
    const int s  = blockIdx.y;
    const int h0 = blockIdx.x * BN;
    const int r0 = s * RB;

    const int tm0 = (tid >> 4) << 2;
    const int tn  = (tid & 15) << 2;

    const int a_r = tid >> 2;
    const int a_k = (tid & 3) << 2;

    const float* Arow  = A   + ((size_t)a_r * RS + s) * RI;
    const float* Wrow0 = Wih + (size_t)(h0 + a_r) * RI;
    const float* Wrow1 = Wih + (size_t)(h0 + 64 + a_r) * RI;

    unsigned long long c2[4][4];
    #pragma unroll
    for (int i = 0; i < 4; i++)
        #pragma unroll
        for (int j = 0; j < 4; j++) c2[i][j] = 0ull;

    for (int k0 = 0; k0 < RI; k0 += BK) {
        float4 av = *reinterpret_cast<const float4*>(Arow  + k0 + a_k);
        float4 w0 = *reinterpret_cast<const float4*>(Wrow0 + k0 + a_k);
        float4 w1 = *reinterpret_cast<const float4*>(Wrow1 + k0 + a_k);
        As[(a_k + 0) * AS_PITCH + a_r] = av.x;
        As[(a_k + 1) * AS_PITCH + a_r] = av.y;
        As[(a_k + 2) * AS_PITCH + a_r] = av.z;
        As[(a_k + 3) * AS_PITCH + a_r] = av.w;
        Ws[(a_k + 0) * WS_PITCH + a_r] = w0.x;
        Ws[(a_k + 1) * WS_PITCH + a_r] = w0.y;
        Ws[(a_k + 2) * WS_PITCH + a_r] = w0.z;
        Ws[(a_k + 3) * WS_PITCH + a_r] = w0.w;
        Ws[(a_k + 0) * WS_PITCH + 64 + a_r] = w1.x;
        Ws[(a_k + 1) * WS_PITCH + 64 + a_r] = w1.y;
        Ws[(a_k + 2) * WS_PITCH + 64 + a_r] = w1.z;
        Ws[(a_k + 3) * WS_PITCH + 64 + a_r] = w1.w;
        __syncthreads();
        #pragma unroll
        for (int kk = 0; kk < BK; kk++) {
            float4 a = *reinterpret_cast<const float4*>(&As[kk * AS_PITCH + tm0]);
            ulonglong2 bA = *reinterpret_cast<const ulonglong2*>(&Ws[kk * WS_PITCH + tn]);
            ulonglong2 bB = *reinterpret_cast<const ulonglong2*>(&Ws[kk * WS_PITCH + 64 + tn]);
            unsigned long long am0 = dup2(a.x), am1 = dup2(a.y),
                               am2 = dup2(a.z), am3 = dup2(a.w);
            ffma2(c2[0][0], am0, bA.x); ffma2(c2[0][1], am0, bA.y);
            ffma2(c2[0][2], am0, bB.x); ffma2(c2[0][3], am0, bB.y);
            ffma2(c2[1][0], am1, bA.x); ffma2(c2[1][1], am1, bA.y);
            ffma2(c2[1][2], am1, bB.x); ffma2(c2[1][3], am1, bB.y);
            ffma2(c2[2][0], am2, bA.x); ffma2(c2[2][1], am2, bA.y);
            ffma2(c2[2][2], am2, bB.x); ffma2(c2[2][3], am2, bB.y);
            ffma2(c2[3][0], am3, bA.x); ffma2(c2[3][1], am3, bA.y);
            ffma2(c2[3][2], am3, bB.x); ffma2(c2[3][3], am3, bB.y);
        }
        __syncthreads();
    }

    const int hA = h0 + tn;
    const int hB = h0 + 64 + tn;
    float4 biA, biB;
    {
        float4 b1 = *reinterpret_cast<const float4*>(bih + hA);
        float4 b2 = *reinterpret_cast<const float4*>(bhh + hA);
        biA = make_float4(b1.x + b2.x, b1.y + b2.y, b1.z + b2.z, b1.w + b2.w);
        float4 b3 = *reinterpret_cast<const float4*>(bih + hB);
        float4 b4 = *reinterpret_cast<const float4*>(bhh + hB);
        biB = make_float4(b3.x + b4.x, b3.y + b4.y, b3.z + b4.z, b3.w + b4.w);
    }
    #pragma unroll
    for (int im = 0; im < 4; im++) {
        int r = r0 + tm0 + im;
        float2 uA0 = unpack2(c2[im][0]);
        float2 uA1 = unpack2(c2[im][1]);
        float2 uB0 = unpack2(c2[im][2]);
        float2 uB1 = unpack2(c2[im][3]);
        float4 oA = make_float4(uA0.x + biA.x, uA0.y + biA.y, uA1.x + biA.z, uA1.y + biA.w);
        float4 oB = make_float4(uB0.x + biB.x, uB0.y + biB.y, uB1.x + biB.z, uB1.y + biB.w);
        *reinterpret_cast<float4*>(&out[(size_t)r * RH + hA]) = oA;
        *reinterpret_cast<float4*>(&out[(size_t)r * RH + hB]) = oB;
    }
}

// ---------------------------------------------------------------------------
// Phase 2: recurrence, NO clusters / NO DSMEM. 128 plain CTAs in 16 groups
// of 8; h exchanged via L2 (__device__ scratch) with flag-based release/
// acquire sync. W_hh register-resident, 512 threads/CTA, 1 CTA/SM.
// Scratch is triple-buffered (mod 3) so a 1-step-lagging reader can never
// race an overwrite. Flags zeroed by an init kernel each launch.
// ---------------------------------------------------------------------------
#define NGRP 16
#define GRP  8
#define HBUF_F4 544     // 4 b * 8 kg blocks * 17 float4

__device__ float    g_hbuf[NGRP][3][GRP][256];  // 384 KB scratch in GMEM/L2
__device__ unsigned g_flag[NGRP][GRP];

__global__ void rnn_init_flags() {
    int t = threadIdx.x;
    if (t < NGRP * GRP) ((unsigned*)g_flag)[t] = 0u;
}

__device__ __forceinline__ void release_flag(unsigned* p, unsigned v) {
    asm volatile("fence.acq_rel.gpu;" ::: "memory");
    asm volatile("st.relaxed.gpu.global.u32 [%0], %1;" :: "l"(p), "r"(v) : "memory");
}
__device__ __forceinline__ void wait_flag(const unsigned* p, unsigned target) {
    unsigned v;
    do {
        asm volatile("ld.acquire.gpu.global.u32 %0, [%1];" : "=r"(v) : "l"(p) : "memory");
    } while (v < target);
}

__global__ void __launch_bounds__(512, 1)
rnn_recur(const float* __restrict__ w_hh,
          const float* __restrict__ state,
          float* __restrict__ out,
          int has_tail)
{
    __shared__ float4 Hv[2 * HBUF_F4];

    const int tid = threadIdx.x;
    const int w = tid >> 5;
    const int l = tid & 31;
    const int r = blockIdx.x & 7;     // rank in group: owns j rows [r*64, r*64+64)
    const int g = blockIdx.x >> 3;    // group: owns batches [g*4, g*4+4)
    const int j0 = r * 64;
    const int b0 = g * 4;

    const int jj = l & 3;
    const int kg = l >> 2;
    const int j_local = (w << 2) + jj;

    // --- W_hh slice into registers: 64 floats per lane ---
    unsigned long long wreg[32];
    {
        const ulonglong2* ws = reinterpret_cast<const ulonglong2*>(
            w_hh + ((size_t)(j0 + j_local) << 9) + ((size_t)kg << 6));
        #pragma unroll
        for (int i = 0; i < 16; i++) {
            ulonglong2 v = ws[i];
            wreg[2 * i]     = v.x;
            wreg[2 * i + 1] = v.y;
        }
    }

    // --- initial state into buf0 ---
    for (int v = tid; v < 4 * 128; v += 512) {
        int b  = v >> 7;
        int kv = v & 127;
        float4 x = __ldg(reinterpret_cast<const float4*>(state) + ((size_t)(b0 + b) << 7) + kv);
        Hv[((b << 3) + (kv >> 4)) * 17 + (kv & 15)] = x;
    }
    __syncthreads();

    const bool act = (l < 16);
    const int ob = l >> 2;
    const size_t row_stride = (size_t)RB * RH;
    const size_t oidx = (size_t)(b0 + ob) * RH + (size_t)(j0 + j_local);
    const int kglob = j0 + j_local;

    // local next-buffer slot for this act lane's y (float index)
    const int loc_fidx = ((ob << 3) + r) * 68 + j_local;
    float* Hv_f = reinterpret_cast<float*>(Hv);

    // loader mapping: thread t pulls one float4 of peer p's slice
    const int p    = tid >> 6;        // peer rank 0..7
    const int c    = tid & 63;
    const int lb   = c >> 4;          // batch 0..3
    const int li   = c & 15;          // f4 index within (b,p) block
    const int dst_f4 = (lb * 8 + p) * 17 + li;
    const bool is_self = (p == r);

    const int offb0 = (kg) * 17;
    const int offb1 = (8 + kg) * 17;
    const int offb2 = (16 + kg) * 17;
    const int offb3 = (24 + kg) * 17;

    float xp_cur = act ? __ldg(out + oidx) : 0.f;

    int cur = 0;
    for (int s = 0; s < RS; ++s) {
        const int nxt = cur ^ 1;
        const int sl = (s + 1) % 3;   // scratch slot for step-(s+1) data

        const float4* base = Hv + cur * HBUF_F4;
        unsigned long long p0 = 0ull, p1 = 0ull, p2 = 0ull, p3 = 0ull;
        unsigned long long q0 = 0ull, q1 = 0ull, q2 = 0ull, q3 = 0ull;
        #pragma unroll
        for (int i = 0; i < 16; i++) {
            ulonglong2 h0 = *reinterpret_cast<const ulonglong2*>(base + offb0 + i);
            ulonglong2 h1 = *reinterpret_cast<const ulonglong2*>(base + offb1 + i);
            ulonglong2 h2 = *reinterpret_cast<const ulonglong2*>(base + offb2 + i);
            ulonglong2 h3 = *reinterpret_cast<const ulonglong2*>(base + offb3 + i);
            unsigned long long w0 = wreg[2 * i], w1 = wreg[2 * i + 1];
            ffma2(p0, w0, h0.x); ffma2(q0, w1, h0.y);
            ffma2(p1, w0, h1.x); ffma2(q1, w1, h1.y);
            ffma2(p2, w0, h2.x); ffma2(q2, w1, h2.y);
            ffma2(p3, w0, h3.x); ffma2(q3, w1, h3.y);
        }
        float a0 = lo_plus_hi(p0) + lo_plus_hi(q0);
        float a1 = lo_plus_hi(p1) + lo_plus_hi(q1);
        float a2 = lo_plus_hi(p2) + lo_plus_hi(q2);
        float a3 = lo_plus_hi(p3) + lo_plus_hi(q3);
        #pragma unroll
        for (int off = 4; off < 32; off <<= 1) {
            a0 += __shfl_xor_sync(0xffffffffu, a0, off);
            a1 += __shfl_xor_sync(0xffffffffu, a1, off);
            a2 += __shfl_xor_sync(0xffffffffu, a2, off);
            a3 += __shfl_xor_sync(0xffffffffu, a3, off);
        }

        float y = 0.f;
        if (act) {
            float acc = (ob == 0) ? a0 : ((ob == 1) ? a1 : ((ob == 2) ? a2 : a3));
            y = tanhf(xp_cur + acc);
            // publish to L2 scratch (for peers) and to local next buffer
            g_hbuf[g][sl][r][ob * 64 + j_local] = y;
            Hv_f[nxt * (HBUF_F4 * 4) + loc_fidx] = y;
        }

        __syncthreads();   // all data stores issued (CTA-wide) before flag

        if (s + 1 < RS) {
            if (tid == 0)
                release_flag(&g_flag[g][r], (unsigned)(s + 1));

            // GMEM work in the wait shadow
            float xp_next = 0.f;
            if (act) {
                out[oidx + (size_t)s * row_stride] = y;
                xp_next = __ldg(out + oidx + (size_t)(s + 1) * row_stride);
            }

            // pull peers' slices from L2 into Hv[nxt]
            if (!is_self) {
                wait_flag(&g_flag[g][p], (unsigned)(s + 1));
                float4 v = __ldcg(reinterpret_cast<const float4*>(
                    &g_hbuf[g][sl][p][lb * 64 + li * 4]));
                Hv[nxt * HBUF_F4 + dst_f4] = v;
            }

            __syncthreads();   // Hv[nxt] complete
            xp_cur = xp_next;
        } else {
            if (act) {
                out[oidx + (size_t)s * row_stride] = y;
                if (has_tail)
                    out[(size_t)RS * RB * RH + (size_t)kglob * RB + (size_t)(b0 + ob)] = y;
            }
        }

        cur = nxt;
    }
}

// ---------------------------------------------------------------------------
// Launch
// ---------------------------------------------------------------------------
extern "C" void kernel_launch(void* const* d_in, const int* in_sizes, int n_in,
                              void* d_out, int out_size)
{
    const float* inputs = (const float*)d_in[0];
    const float* state  = (const float*)d_in[1];
    const float* w_ih   = (const float*)d_in[2];
    const float* b_ih   = (const float*)d_in[3];
    const float* w_hh   = (const float*)d_in[4];
    const float* b_hh   = (const float*)d_in[5];
    float* out = (float*)d_out;

    rnn_init_flags<<<1, 128>>>();

    dim3 g1(RH / BN, RS);   // (4, 2048)
    rnn_xproj<<<g1, 256>>>(inputs, w_ih, b_ih, b_hh, out);

    int has_tail = (out_size > RS * RB * RH) ? 1 : 0;
    rnn_recur<<<128, 512>>>(w_hh, state, out, has_tail);
}

// round 6
// speedup vs baseline: 1.3258x; 1.1981x over previous
#include <cuda_runtime.h>
#include <cstdint>
#include <cstddef>

// Problem constants
#define RH 512
#define RB 64
#define RS 2048
#define RI 512

// ---------------------------------------------------------------------------
// f32x2 packed helpers (sm_100a)
// ---------------------------------------------------------------------------
__device__ __forceinline__ void ffma2(unsigned long long &d,
                                      unsigned long long a,
                                      unsigned long long b) {
    asm("fma.rn.f32x2 %0, %1, %2, %0;" : "+l"(d) : "l"(a), "l"(b));
}
__device__ __forceinline__ unsigned long long dup2(float x) {
    unsigned long long r;
    asm("mov.b64 %0, {%1, %1};" : "=l"(r) : "f"(x));
    return r;
}
__device__ __forceinline__ float2 unpack2(unsigned long long v) {
    float2 r;
    asm("mov.b64 {%0, %1}, %2;" : "=f"(r.x), "=f"(r.y) : "l"(v));
    return r;
}
__device__ __forceinline__ float lo_plus_hi(unsigned long long v) {
    float2 r = unpack2(v);
    return r.x + r.y;
}

// ---------------------------------------------------------------------------
// Phase 1: x_proj GEMM (unchanged)
// ---------------------------------------------------------------------------
#define BN 128
#define BK 16
#define AS_PITCH 68
#define WS_PITCH 136

__global__ void __launch_bounds__(256)
rnn_xproj(const float* __restrict__ A,
          const float* __restrict__ Wih,
          const float* __restrict__ bih,
          const float* __restrict__ bhh,
          float* __restrict__ out)
{
    __shared__ float As[BK * AS_PITCH];
    __shared__ float Ws[BK * WS_PITCH];

    const int tid = threadIdx.x;
    const int s  = blockIdx.y;
    const int h0 = blockIdx.x * BN;
    const int r0 = s * RB;

    const int tm0 = (tid >> 4) << 2;
    const int tn  = (tid & 15) << 2;

    const int a_r = tid >> 2;
    const int a_k = (tid & 3) << 2;

    const float* Arow  = A   + ((size_t)a_r * RS + s) * RI;
    const float* Wrow0 = Wih + (size_t)(h0 + a_r) * RI;
    const float* Wrow1 = Wih + (size_t)(h0 + 64 + a_r) * RI;

    unsigned long long c2[4][4];
    #pragma unroll
    for (int i = 0; i < 4; i++)
        #pragma unroll
        for (int j = 0; j < 4; j++) c2[i][j] = 0ull;

    for (int k0 = 0; k0 < RI; k0 += BK) {
        float4 av = *reinterpret_cast<const float4*>(Arow  + k0 + a_k);
        float4 w0 = *reinterpret_cast<const float4*>(Wrow0 + k0 + a_k);
        float4 w1 = *reinterpret_cast<const float4*>(Wrow1 + k0 + a_k);
        As[(a_k + 0) * AS_PITCH + a_r] = av.x;
        As[(a_k + 1) * AS_PITCH + a_r] = av.y;
        As[(a_k + 2) * AS_PITCH + a_r] = av.z;
        As[(a_k + 3) * AS_PITCH + a_r] = av.w;
        Ws[(a_k + 0) * WS_PITCH + a_r] = w0.x;
        Ws[(a_k + 1) * WS_PITCH + a_r] = w0.y;
        Ws[(a_k + 2) * WS_PITCH + a_r] = w0.z;
        Ws[(a_k + 3) * WS_PITCH + a_r] = w0.w;
        Ws[(a_k + 0) * WS_PITCH + 64 + a_r] = w1.x;
        Ws[(a_k + 1) * WS_PITCH + 64 + a_r] = w1.y;
        Ws[(a_k + 2) * WS_PITCH + 64 + a_r] = w1.z;
        Ws[(a_k + 3) * WS_PITCH + 64 + a_r] = w1.w;
        __syncthreads();
        #pragma unroll
        for (int kk = 0; kk < BK; kk++) {
            float4 a = *reinterpret_cast<const float4*>(&As[kk * AS_PITCH + tm0]);
            ulonglong2 bA = *reinterpret_cast<const ulonglong2*>(&Ws[kk * WS_PITCH + tn]);
            ulonglong2 bB = *reinterpret_cast<const ulonglong2*>(&Ws[kk * WS_PITCH + 64 + tn]);
            unsigned long long am0 = dup2(a.x), am1 = dup2(a.y),
                               am2 = dup2(a.z), am3 = dup2(a.w);
            ffma2(c2[0][0], am0, bA.x); ffma2(c2[0][1], am0, bA.y);
            ffma2(c2[0][2], am0, bB.x); ffma2(c2[0][3], am0, bB.y);
            ffma2(c2[1][0], am1, bA.x); ffma2(c2[1][1], am1, bA.y);
            ffma2(c2[1][2], am1, bB.x); ffma2(c2[1][3], am1, bB.y);
            ffma2(c2[2][0], am2, bA.x); ffma2(c2[2][1], am2, bA.y);
            ffma2(c2[2][2], am2, bB.x); ffma2(c2[2][3], am2, bB.y);
            ffma2(c2[3][0], am3, bA.x); ffma2(c2[3][1], am3, bA.y);
            ffma2(c2[3][2], am3, bB.x); ffma2(c2[3][3], am3, bB.y);
        }
        __syncthreads();
    }

    const int hA = h0 + tn;
    const int hB = h0 + 64 + tn;
    float4 biA, biB;
    {
        float4 b1 = *reinterpret_cast<const float4*>(bih + hA);
        float4 b2 = *reinterpret_cast<const float4*>(bhh + hA);
        biA = make_float4(b1.x + b2.x, b1.y + b2.y, b1.z + b2.z, b1.w + b2.w);
        float4 b3 = *reinterpret_cast<const float4*>(bih + hB);
        float4 b4 = *reinterpret_cast<const float4*>(bhh + hB);
        biB = make_float4(b3.x + b4.x, b3.y + b4.y, b3.z + b4.z, b3.w + b4.w);
    }
    #pragma unroll
    for (int im = 0; im < 4; im++) {
        int r = r0 + tm0 + im;
        float2 uA0 = unpack2(c2[im][0]);
        float2 uA1 = unpack2(c2[im][1]);
        float2 uB0 = unpack2(c2[im][2]);
        float2 uB1 = unpack2(c2[im][3]);
        float4 oA = make_float4(uA0.x + biA.x, uA0.y + biA.y, uA1.x + biA.z, uA1.y + biA.w);
        float4 oB = make_float4(uB0.x + biB.x, uB0.y + biB.y, uB1.x + biB.z, uB1.y + biB.w);
        *reinterpret_cast<float4*>(&out[(size_t)r * RH + hA]) = oA;
        *reinterpret_cast<float4*>(&out[(size_t)r * RH + hB]) = oB;
    }
}

// ---------------------------------------------------------------------------
// Phase 2: recurrence. 16 clusters x 8 CTAs, 512 threads/CTA.
// FENCE-FREE exchange: every thread does one st.shared::cluster.v4 followed by
// its OWN mbarrier.arrive.release.cluster on the target's (slot,src) bar —
// release covers exactly that thread's store, so no cluster fence / no
// CCTL.IVALL / no store drain on the critical path. Triple-buffered Hv
// (skew<=1 by data dependency => 3 slots are overwrite-safe). Consumer:
// warp-0 lanes 0-7 try_wait the 8 source bars, then __syncthreads.
// ---------------------------------------------------------------------------
#define CSZ 8
#define HBUF_F4 544                 // 4 b * 8 kg blocks * 17 float4 per slot
#define STAGE_F4 68

__device__ __forceinline__ uint32_t smem_u32(const void* p) {
    return (uint32_t)__cvta_generic_to_shared(p);
}
__device__ __forceinline__ uint32_t mapa_u32(uint32_t addr, uint32_t rank) {
    uint32_t r;
    asm("mapa.shared::cluster.u32 %0, %1, %2;" : "=r"(r) : "r"(addr), "r"(rank));
    return r;
}
__device__ __forceinline__ void st_cluster_v4(uint32_t addr, float4 v) {
    asm volatile("st.shared::cluster.v4.f32 [%0], {%1,%2,%3,%4};"
                 :: "r"(addr), "f"(v.x), "f"(v.y), "f"(v.z), "f"(v.w) : "memory");
}
__device__ __forceinline__ void mbar_init(uint32_t addr, uint32_t count) {
    asm volatile("mbarrier.init.shared.b64 [%0], %1;" :: "r"(addr), "r"(count) : "memory");
}
__device__ __forceinline__ void mbar_arrive_release_cluster(uint32_t addr) {
    asm volatile("mbarrier.arrive.release.cluster.shared::cluster.b64 _, [%0];"
                 :: "r"(addr) : "memory");
}
__device__ __forceinline__ void mbar_wait_parity_acq_cluster(uint32_t addr, uint32_t parity) {
    uint32_t done;
    asm volatile(
        "{\n\t"
        ".reg .pred p;\n\t"
        "mbarrier.try_wait.parity.acquire.cluster.shared::cta.b64 p, [%1], %2;\n\t"
        "selp.b32 %0, 1, 0, p;\n\t"
        "}"
        : "=r"(done) : "r"(addr), "r"(parity) : "memory");
    if (!done) {
        asm volatile(
            "{\n\t"
            ".reg .pred P1;\n\t"
            "WAIT_LOOP_%=:\n\t"
            "mbarrier.try_wait.parity.acquire.cluster.shared::cta.b64 P1, [%0], %1, 0x989680;\n\t"
            "@P1 bra.uni WAIT_DONE_%=;\n\t"
            "bra.uni WAIT_LOOP_%=;\n\t"
            "WAIT_DONE_%=:\n\t"
            "}"
            :: "r"(addr), "r"(parity) : "memory");
    }
}
__device__ __forceinline__ void cluster_sync_once() {
    asm volatile("barrier.cluster.arrive.aligned;" ::: "memory");
    asm volatile("barrier.cluster.wait.aligned;" ::: "memory");
}

__global__ void __cluster_dims__(CSZ, 1, 1) __launch_bounds__(512, 1)
rnn_recur(const float* __restrict__ w_hh,
          const float* __restrict__ state,
          float* __restrict__ out,
          int has_tail)
{
    __shared__ float4 Hv[3 * HBUF_F4];
    __shared__ float4 Stg[STAGE_F4];
    __shared__ alignas(8) unsigned long long bars[3 * CSZ];  // [slot][src]

    const int tid = threadIdx.x;
    const int w = tid >> 5;
    const int l = tid & 31;
    uint32_t rank;
    asm("mov.u32 %0, %%cluster_ctarank;" : "=r"(rank));
    const int cl = blockIdx.x >> 3;
    const int j0 = (int)rank * 64;
    const int b0 = cl * 4;

    const int jj = l & 3;
    const int kg = l >> 2;
    const int j_local = (w << 2) + jj;

    // --- W_hh slice into registers ---
    unsigned long long wreg[32];
    {
        const ulonglong2* ws = reinterpret_cast<const ulonglong2*>(
            w_hh + ((size_t)(j0 + j_local) << 9) + ((size_t)kg << 6));
        #pragma unroll
        for (int i = 0; i < 16; i++) {
            ulonglong2 v = ws[i];
            wreg[2 * i]     = v.x;
            wreg[2 * i + 1] = v.y;
        }
    }

    // --- initial state into slot 0 ---
    for (int v = tid; v < 4 * 128; v += 512) {
        int b  = v >> 7;
        int kv = v & 127;
        float4 x = __ldg(reinterpret_cast<const float4*>(state) + ((size_t)(b0 + b) << 7) + kv);
        Hv[((b << 3) + (kv >> 4)) * 17 + (kv & 15)] = x;
    }
    // --- init 24 mbarriers: 64 arrivals per phase each ---
    if (tid < 3 * CSZ) mbar_init(smem_u32(&bars[tid]), 64);
    __syncthreads();
    cluster_sync_once();   // slot0 + bars visible cluster-wide before any traffic

    const bool act = (l < 16);
    const int ob = l >> 2;
    const size_t row_stride = (size_t)RB * RH;
    const size_t oidx = (size_t)(b0 + ob) * RH + (size_t)(j0 + j_local);
    const int kglob = j0 + j_local;

    float* stg_f = reinterpret_cast<float*>(Stg);
    const int stg_idx = ob * 68 + j_local;

    // publish mapping: thread moves one float4 to CTA bc_c each step
    const int bc_c   = tid >> 6;          // target CTA rank 0..7
    const int bc_idx = tid & 63;
    const int bc_ob  = bc_idx >> 4;
    const int bc_i   = bc_idx & 15;
    const int src_f4 = bc_ob * 17 + bc_i;
    const uint32_t dst_off = (uint32_t)((((bc_ob << 3) + (int)rank) * 17 + bc_i) * 16);
    const uint32_t remData = mapa_u32(smem_u32(Hv) + dst_off, (uint32_t)bc_c);
    const uint32_t remBars = mapa_u32(smem_u32(bars), (uint32_t)bc_c);
    const uint32_t localBars = smem_u32(bars);
    const uint32_t bufBytes = HBUF_F4 * 16u;

    const int offb0 = (kg) * 17;
    const int offb1 = (8 + kg) * 17;
    const int offb2 = (16 + kg) * 17;
    const int offb3 = (24 + kg) * 17;

    float xp_cur = act ? __ldg(out + oidx) : 0.f;

    int slot = 0, nslot = 1;
    for (int s = 0; s < RS; ++s) {
        if (s > 0) {
            // wait for all 8 sources' publishes into Hv[slot]
            if (tid < CSZ) {
                uint32_t pw = (uint32_t)(((s - 1) / 3) & 1);
                mbar_wait_parity_acq_cluster(localBars + (uint32_t)(slot * CSZ + tid) * 8u, pw);
            }
            __syncthreads();
        }

        const float4* base = Hv + slot * HBUF_F4;
        unsigned long long p0 = 0ull, p1 = 0ull, p2 = 0ull, p3 = 0ull;
        unsigned long long q0 = 0ull, q1 = 0ull, q2 = 0ull, q3 = 0ull;
        #pragma unroll
        for (int i = 0; i < 16; i++) {
            ulonglong2 h0 = *reinterpret_cast<const ulonglong2*>(base + offb0 + i);
            ulonglong2 h1 = *reinterpret_cast<const ulonglong2*>(base + offb1 + i);
            ulonglong2 h2 = *reinterpret_cast<const ulonglong2*>(base + offb2 + i);
            ulonglong2 h3 = *reinterpret_cast<const ulonglong2*>(base + offb3 + i);
            unsigned long long w0 = wreg[2 * i], w1 = wreg[2 * i + 1];
            ffma2(p0, w0, h0.x); ffma2(q0, w1, h0.y);
            ffma2(p1, w0, h1.x); ffma2(q1, w1, h1.y);
            ffma2(p2, w0, h2.x); ffma2(q2, w1, h2.y);
            ffma2(p3, w0, h3.x); ffma2(q3, w1, h3.y);
        }
        float a0 = lo_plus_hi(p0) + lo_plus_hi(q0);
        float a1 = lo_plus_hi(p1) + lo_plus_hi(q1);
        float a2 = lo_plus_hi(p2) + lo_plus_hi(q2);
        float a3 = lo_plus_hi(p3) + lo_plus_hi(q3);
        #pragma unroll
        for (int off = 4; off < 32; off <<= 1) {
            a0 += __shfl_xor_sync(0xffffffffu, a0, off);
            a1 += __shfl_xor_sync(0xffffffffu, a1, off);
            a2 += __shfl_xor_sync(0xffffffffu, a2, off);
            a3 += __shfl_xor_sync(0xffffffffu, a3, off);
        }

        float y = 0.f;
        if (act) {
            float acc = (ob == 0) ? a0 : ((ob == 1) ? a1 : ((ob == 2) ? a2 : a3));
            y = tanhf(xp_cur + acc);
            stg_f[stg_idx] = y;
        }

        __syncthreads();   // staging complete

        if (s + 1 < RS) {
            // publish: one v4 store + one release-arrive per thread (no fence)
            float4 v = Stg[src_f4];
            st_cluster_v4(remData + (uint32_t)nslot * bufBytes, v);
            mbar_arrive_release_cluster(remBars + (uint32_t)(nslot * CSZ + (int)rank) * 8u);
        }

        // GMEM traffic between publish and next wait
        float xp_next = 0.f;
        if (act) {
            out[oidx + (size_t)s * row_stride] = y;
            if (has_tail && (s == RS - 1))
                out[(size_t)RS * RB * RH + (size_t)kglob * RB + (size_t)(b0 + ob)] = y;
            if (s + 1 < RS)
                xp_next = __ldg(out + oidx + (size_t)(s + 1) * row_stride);
        }

        slot = nslot;
        nslot = nslot + 1; if (nslot == 3) nslot = 0;
        xp_cur = xp_next;
    }
}

// ---------------------------------------------------------------------------
// Launch
// ---------------------------------------------------------------------------
extern "C" void kernel_launch(void* const* d_in, const int* in_sizes, int n_in,
                              void* d_out, int out_size)
{
    const float* inputs = (const float*)d_in[0];
    const float* state  = (const float*)d_in[1];
    const float* w_ih   = (const float*)d_in[2];
    const float* b_ih   = (const float*)d_in[3];
    const float* w_hh   = (const float*)d_in[4];
    const float* b_hh   = (const float*)d_in[5];
    float* out = (float*)d_out;

    dim3 g1(RH / BN, RS);   // (4, 2048)
    rnn_xproj<<<g1, 256>>>(inputs, w_ih, b_ih, b_hh, out);

    int has_tail = (out_size > RS * RB * RH) ? 1 : 0;
    rnn_recur<<<128, 512>>>(w_hh, state, out, has_tail);
}